// round 3
// baseline (speedup 1.0000x reference)
#include <cuda_runtime.h>
#include <math.h>

// Problem shapes (fixed by setup_inputs)
#define B  4
#define N1 1024
#define N2 4096
#define MAXITER 10

// Output layout (floats):
// [0, 12288)          output1 passthrough
// [12288, 61440)      output2 passthrough
// [61440, 61444)      emd1
// [61444, 61448)      emd2
// [61448, 61452)      cd_p1
// [61452, 61456)      cd_p2
// [61456, 61460)      cd_t1
// [61460, 61464)      cd_t2
#define OUT_SCALARS 61440

// ---------------------------------------------------------------------------
// Scratch (device globals; no allocations allowed)
// ---------------------------------------------------------------------------
__device__ float  g_gtfps[B * N1 * 3];
__device__ float  g_f1[B * N1];
__device__ float  g_g1[B * N1];
__device__ float  g_f2[B * N2];
__device__ float  g_g2[B * N2];
__device__ float  g_emd1p[B * (N1 / 128)];
__device__ float  g_emd2p[B * (N2 / 128)];
__device__ float2 g_d11p[B * (N2 / 128)];   // gt -> output1
__device__ float2 g_d12p[B * (N1 / 128)];   // output1 -> gt
__device__ float2 g_d21p[B * (N2 / 128)];   // gt -> output2
__device__ float2 g_d22p[B * (N2 / 128)];   // output2 -> gt
__device__ int    g_default_iters = MAXITER;

// ---------------------------------------------------------------------------
// Zero-init Sinkhorn potentials
// ---------------------------------------------------------------------------
__global__ void zero_kernel(float* f1, float* f2) {
    int i = blockIdx.x * blockDim.x + threadIdx.x;
    if (i < B * N1) f1[i] = 0.0f;
    if (i < B * N2) f2[i] = 0.0f;
}

// ---------------------------------------------------------------------------
// FPS: 1 block of 1024 threads per batch. Sequential 1023-step argmax.
// dists in registers (4 per thread), points in SMEM.
// Exactly matches the reference: difference-form squared distance, argmax
// with first-index tiebreak, start index 0.
// ---------------------------------------------------------------------------
__global__ __launch_bounds__(1024, 1)
void fps_kernel(const float* __restrict__ gt, float* __restrict__ gtfps) {
    extern __shared__ float sm[];
    float* spts = sm;                       // N2*3 floats
    float* wval = sm + N2 * 3;              // 32
    int*   widx = (int*)(wval + 32);        // 32
    float* ssel = (float*)(widx + 32);      // 3

    int b = blockIdx.x;
    const float* pts = gt + (size_t)b * N2 * 3;
    int tid = threadIdx.x;

    for (int i = tid; i < N2 * 3; i += blockDim.x) spts[i] = pts[i];
    __syncthreads();

    float x0 = spts[0], y0 = spts[1], z0 = spts[2];
    float px[4], py[4], pz[4], d[4];
#pragma unroll
    for (int c = 0; c < 4; c++) {
        int k = tid + c * 1024;
        px[c] = spts[3 * k];
        py[c] = spts[3 * k + 1];
        pz[c] = spts[3 * k + 2];
        float dx = px[c] - x0, dy = py[c] - y0, dz = pz[c] - z0;
        d[c] = dx * dx + dy * dy + dz * dz;
    }

    float* outp = gtfps + (size_t)b * N1 * 3;
    if (tid == 0) { outp[0] = x0; outp[1] = y0; outp[2] = z0; }

    int lane = tid & 31, warp = tid >> 5;
    for (int t = 1; t < N1; t++) {
        // local argmax over my 4 (ascending index -> strict > keeps first)
        float bv = d[0]; int bi = tid;
#pragma unroll
        for (int c = 1; c < 4; c++) {
            int k = tid + c * 1024;
            if (d[c] > bv) { bv = d[c]; bi = k; }
        }
        // warp butterfly argmax, lower index wins ties
#pragma unroll
        for (int off = 16; off >= 1; off >>= 1) {
            float ov = __shfl_xor_sync(0xffffffffu, bv, off);
            int   oi = __shfl_xor_sync(0xffffffffu, bi, off);
            if (ov > bv || (ov == bv && oi < bi)) { bv = ov; bi = oi; }
        }
        if (lane == 0) { wval[warp] = bv; widx[warp] = bi; }
        __syncthreads();
        if (warp == 0) {
            bv = wval[lane]; bi = widx[lane];
#pragma unroll
            for (int off = 16; off >= 1; off >>= 1) {
                float ov = __shfl_xor_sync(0xffffffffu, bv, off);
                int   oi = __shfl_xor_sync(0xffffffffu, bi, off);
                if (ov > bv || (ov == bv && oi < bi)) { bv = ov; bi = oi; }
            }
            if (lane == 0) {
                float sx = spts[3 * bi], sy = spts[3 * bi + 1], sz = spts[3 * bi + 2];
                ssel[0] = sx; ssel[1] = sy; ssel[2] = sz;
                outp[3 * t] = sx; outp[3 * t + 1] = sy; outp[3 * t + 2] = sz;
            }
        }
        __syncthreads();
        float sx = ssel[0], sy = ssel[1], sz = ssel[2];
#pragma unroll
        for (int c = 0; c < 4; c++) {
            float dx = px[c] - sx, dy = py[c] - sy, dz = pz[c] - sz;
            float dd = dx * dx + dy * dy + dz * dz;
            d[c] = fminf(d[c], dd);
        }
    }
}

// ---------------------------------------------------------------------------
// One Sinkhorn half-step: vout[j] = -eps * LSE_k( (vred_k - C_kj)/eps + loga )
// C is recomputed on the fly (unclamped; clamp deviates only by fp noise/eps,
// far below tolerance). Tile: {x, y, z, (vred - ||p||^2)/eps}; per-output
// constant -||q||^2/eps + loga folded at the end.
// grid (n/128, B), block 128, smem = n * 16 bytes.
// t >= 0: iteration index guarded against *iters_p. t < 0: always run.
// ---------------------------------------------------------------------------
__global__ __launch_bounds__(128)
void lse_kernel(const float* __restrict__ Pout, const float* __restrict__ Pred,
                const float* __restrict__ vred, float* __restrict__ vout,
                int n, const float* __restrict__ eps_p,
                const int* __restrict__ iters_p, int t) {
    if (t >= 0 && t >= __ldg(iters_p)) return;
    extern __shared__ float4 tile[];
    int b = blockIdx.y;
    float eps = __ldg(eps_p);
    float inv_eps = 1.0f / eps;

    const float* Pr = Pred + (size_t)b * n * 3;
    const float* vr = vred + (size_t)b * n;
    for (int k = threadIdx.x; k < n; k += blockDim.x) {
        float x = Pr[3 * k], y = Pr[3 * k + 1], z = Pr[3 * k + 2];
        float na = x * x + y * y + z * z;
        tile[k] = make_float4(x, y, z, (vr[k] - na) * inv_eps);
    }
    __syncthreads();

    int j = blockIdx.x * blockDim.x + threadIdx.x;
    const float* Po = Pout + (size_t)b * n * 3;
    float qx = Po[3 * j], qy = Po[3 * j + 1], qz = Po[3 * j + 2];
    float nb = qx * qx + qy * qy + qz * qz;
    float c1 = 2.0f * inv_eps;

    // pass 1: max of p = c1*dot + u   (4 accumulators for ILP)
    float m0 = -1e30f, m1 = -1e30f, m2 = -1e30f, m3 = -1e30f;
    for (int k = 0; k < n; k += 4) {
        float4 e0 = tile[k + 0], e1 = tile[k + 1], e2 = tile[k + 2], e3 = tile[k + 3];
        float p0 = fmaf(c1, fmaf(e0.x, qx, fmaf(e0.y, qy, e0.z * qz)), e0.w);
        float p1 = fmaf(c1, fmaf(e1.x, qx, fmaf(e1.y, qy, e1.z * qz)), e1.w);
        float p2 = fmaf(c1, fmaf(e2.x, qx, fmaf(e2.y, qy, e2.z * qz)), e2.w);
        float p3 = fmaf(c1, fmaf(e3.x, qx, fmaf(e3.y, qy, e3.z * qz)), e3.w);
        m0 = fmaxf(m0, p0); m1 = fmaxf(m1, p1);
        m2 = fmaxf(m2, p2); m3 = fmaxf(m3, p3);
    }
    float m = fmaxf(fmaxf(m0, m1), fmaxf(m2, m3));

    // pass 2: sum of exp(p - m), skipping exact-underflow terms
    float s0 = 0.f, s1 = 0.f, s2 = 0.f, s3 = 0.f;
    for (int k = 0; k < n; k += 4) {
        float4 e0 = tile[k + 0], e1 = tile[k + 1], e2 = tile[k + 2], e3 = tile[k + 3];
        float p0 = fmaf(c1, fmaf(e0.x, qx, fmaf(e0.y, qy, e0.z * qz)), e0.w) - m;
        float p1 = fmaf(c1, fmaf(e1.x, qx, fmaf(e1.y, qy, e1.z * qz)), e1.w) - m;
        float p2 = fmaf(c1, fmaf(e2.x, qx, fmaf(e2.y, qy, e2.z * qz)), e2.w) - m;
        float p3 = fmaf(c1, fmaf(e3.x, qx, fmaf(e3.y, qy, e3.z * qz)), e3.w) - m;
        if (p0 > -87.0f) s0 += __expf(p0);
        if (p1 > -87.0f) s1 += __expf(p1);
        if (p2 > -87.0f) s2 += __expf(p2);
        if (p3 > -87.0f) s3 += __expf(p3);
    }
    float s = (s0 + s1) + (s2 + s3);
    float loga = -logf((float)n);
    vout[(size_t)b * n + j] = -eps * (m + fmaf(-nb, inv_eps, loga) + logf(s));
}

// ---------------------------------------------------------------------------
// Final assignment: for each x-point i, argmax_j (g_j - C_ij) (f_i constant),
// first-index tiebreak via strict > ascending scan. d = clamped C at argmax.
// Block writes sum(sqrt(d)) over its 128 points to partial.
// smem = n*16 (tile {x,y,z,nb}) + n*4 (g) + 128*4 (reduce)
// ---------------------------------------------------------------------------
__global__ __launch_bounds__(128)
void assign_kernel(const float* __restrict__ Px, const float* __restrict__ Py,
                   const float* __restrict__ gvec, float* __restrict__ partial,
                   int n) {
    extern __shared__ float sm_raw[];
    float4* tile = (float4*)sm_raw;           // n
    float*  sg   = (float*)(tile + n);        // n
    float*  red  = sg + n;                    // 128

    int b = blockIdx.y;
    const float* Pyb = Py + (size_t)b * n * 3;
    const float* gb  = gvec + (size_t)b * n;
    for (int k = threadIdx.x; k < n; k += blockDim.x) {
        float x = Pyb[3 * k], y = Pyb[3 * k + 1], z = Pyb[3 * k + 2];
        tile[k] = make_float4(x, y, z, x * x + y * y + z * z);
        sg[k] = gb[k];
    }
    __syncthreads();

    int i = blockIdx.x * blockDim.x + threadIdx.x;
    const float* Pxb = Px + (size_t)b * n * 3;
    float qx = Pxb[3 * i], qy = Pxb[3 * i + 1], qz = Pxb[3 * i + 2];
    float na = qx * qx + qy * qy + qz * qz;

    float best = -1e30f, bestd = 0.0f;
    for (int k = 0; k < n; k++) {
        float4 e = tile[k];
        float dot = fmaf(e.x, qx, fmaf(e.y, qy, e.z * qz));
        float C = fmaxf(fmaf(-2.0f, dot, na + e.w), 0.0f);
        float sc = sg[k] - C;
        if (sc > best) { best = sc; bestd = C; }
    }

    red[threadIdx.x] = sqrtf(bestd);
    __syncthreads();
    for (int st = 64; st > 0; st >>= 1) {
        if (threadIdx.x < st) red[threadIdx.x] += red[threadIdx.x + st];
        __syncthreads();
    }
    if (threadIdx.x == 0) partial[b * gridDim.x + blockIdx.x] = red[0];
}

// ---------------------------------------------------------------------------
// Chamfer: for each a-point, min over b of clamped sqdist.
// Block writes (sum sqrt(min), sum min) to partial.
// smem = nb_n*16 + 128*8
// ---------------------------------------------------------------------------
__global__ __launch_bounds__(128)
void chamfer_kernel(const float* __restrict__ Pa, const float* __restrict__ Pb,
                    int na_n, int nb_n, float2* __restrict__ partial) {
    extern __shared__ float sm_raw[];
    float4* tile = (float4*)sm_raw;            // nb_n
    float*  red1 = (float*)(tile + nb_n);      // 128 (sqrt sums)
    float*  red2 = red1 + 128;                 // 128 (raw sums)

    int b = blockIdx.y;
    const float* Pbb = Pb + (size_t)b * nb_n * 3;
    for (int k = threadIdx.x; k < nb_n; k += blockDim.x) {
        float x = Pbb[3 * k], y = Pbb[3 * k + 1], z = Pbb[3 * k + 2];
        tile[k] = make_float4(x, y, z, x * x + y * y + z * z);
    }
    __syncthreads();

    int i = blockIdx.x * blockDim.x + threadIdx.x;
    const float* Pab = Pa + (size_t)b * na_n * 3;
    float qx = Pab[3 * i], qy = Pab[3 * i + 1], qz = Pab[3 * i + 2];
    float na = qx * qx + qy * qy + qz * qz;

    float mn0 = 1e30f, mn1 = 1e30f;
    for (int k = 0; k < nb_n; k += 2) {
        float4 e0 = tile[k], e1 = tile[k + 1];
        float d0 = fmaxf(fmaf(-2.0f, fmaf(e0.x, qx, fmaf(e0.y, qy, e0.z * qz)), na + e0.w), 0.0f);
        float d1 = fmaxf(fmaf(-2.0f, fmaf(e1.x, qx, fmaf(e1.y, qy, e1.z * qz)), na + e1.w), 0.0f);
        mn0 = fminf(mn0, d0);
        mn1 = fminf(mn1, d1);
    }
    float mn = fminf(mn0, mn1);

    red1[threadIdx.x] = sqrtf(mn);
    red2[threadIdx.x] = mn;
    __syncthreads();
    for (int st = 64; st > 0; st >>= 1) {
        if (threadIdx.x < st) {
            red1[threadIdx.x] += red1[threadIdx.x + st];
            red2[threadIdx.x] += red2[threadIdx.x + st];
        }
        __syncthreads();
    }
    if (threadIdx.x == 0)
        partial[b * gridDim.x + blockIdx.x] = make_float2(red1[0], red2[0]);
}

// ---------------------------------------------------------------------------
// Finalize: fold partials into the 24 scalar outputs (fixed order, no atomics)
// ---------------------------------------------------------------------------
__global__ void finalize_kernel(float* __restrict__ out) {
    int b = threadIdx.x;
    if (b >= B) return;

    float s = 0.f;
    for (int i = 0; i < N1 / 128; i++) s += g_emd1p[b * (N1 / 128) + i];
    out[OUT_SCALARS + 0 + b] = s / (float)N1;

    s = 0.f;
    for (int i = 0; i < N2 / 128; i++) s += g_emd2p[b * (N2 / 128) + i];
    out[OUT_SCALARS + 4 + b] = s / (float)N2;

    float ss11 = 0.f, s11 = 0.f;
    for (int i = 0; i < N2 / 128; i++) { float2 v = g_d11p[b * (N2 / 128) + i]; ss11 += v.x; s11 += v.y; }
    float ss12 = 0.f, s12 = 0.f;
    for (int i = 0; i < N1 / 128; i++) { float2 v = g_d12p[b * (N1 / 128) + i]; ss12 += v.x; s12 += v.y; }
    out[OUT_SCALARS + 8 + b]  = (ss11 / (float)N2 + ss12 / (float)N1) * 0.5f;   // cd_p1
    out[OUT_SCALARS + 16 + b] =  s11 / (float)N2 + s12 / (float)N1;             // cd_t1

    float ss21 = 0.f, s21 = 0.f;
    for (int i = 0; i < N2 / 128; i++) { float2 v = g_d21p[b * (N2 / 128) + i]; ss21 += v.x; s21 += v.y; }
    float ss22 = 0.f, s22 = 0.f;
    for (int i = 0; i < N2 / 128; i++) { float2 v = g_d22p[b * (N2 / 128) + i]; ss22 += v.x; s22 += v.y; }
    out[OUT_SCALARS + 12 + b] = (ss21 / (float)N2 + ss22 / (float)N2) * 0.5f;   // cd_p2
    out[OUT_SCALARS + 20 + b] =  s21 / (float)N2 + s22 / (float)N2;             // cd_t2
}

// ---------------------------------------------------------------------------
// Launch
// ---------------------------------------------------------------------------
extern "C" void kernel_launch(void* const* d_in, const int* in_sizes, int n_in,
                              void* d_out, int out_size) {
    const float* o1    = (const float*)d_in[0];
    const float* o2    = (const float*)d_in[1];
    const float* gt    = (const float*)d_in[2];
    const float* eps_p = (const float*)d_in[3];
    float* out = (float*)d_out;

    // Scratch pointers
    float *gtfps, *f1, *g1v, *f2, *g2v, *e1p, *e2p;
    float2 *p11, *p12, *p21, *p22;
    int* def_iters;
    cudaGetSymbolAddress((void**)&gtfps, g_gtfps);
    cudaGetSymbolAddress((void**)&f1, g_f1);
    cudaGetSymbolAddress((void**)&g1v, g_g1);
    cudaGetSymbolAddress((void**)&f2, g_f2);
    cudaGetSymbolAddress((void**)&g2v, g_g2);
    cudaGetSymbolAddress((void**)&e1p, g_emd1p);
    cudaGetSymbolAddress((void**)&e2p, g_emd2p);
    cudaGetSymbolAddress((void**)&p11, g_d11p);
    cudaGetSymbolAddress((void**)&p12, g_d12p);
    cudaGetSymbolAddress((void**)&p21, g_d21p);
    cudaGetSymbolAddress((void**)&p22, g_d22p);
    cudaGetSymbolAddress((void**)&def_iters, g_default_iters);

    const int* iters_p = (n_in > 4) ? (const int*)d_in[4] : def_iters;

    // Raise dynamic smem limits (idempotent)
    cudaFuncSetAttribute(fps_kernel,     cudaFuncAttributeMaxDynamicSharedMemorySize, 50176);
    cudaFuncSetAttribute(lse_kernel,     cudaFuncAttributeMaxDynamicSharedMemorySize, 66560);
    cudaFuncSetAttribute(assign_kernel,  cudaFuncAttributeMaxDynamicSharedMemorySize, 84480);
    cudaFuncSetAttribute(chamfer_kernel, cudaFuncAttributeMaxDynamicSharedMemorySize, 67584);

    // Passthrough copies
    cudaMemcpyAsync(out, o1, (size_t)B * N1 * 3 * sizeof(float), cudaMemcpyDeviceToDevice);
    cudaMemcpyAsync(out + B * N1 * 3, o2, (size_t)B * N2 * 3 * sizeof(float), cudaMemcpyDeviceToDevice);

    // FPS (gathers gt_fps coords directly)
    size_t fps_smem = (size_t)N2 * 3 * sizeof(float) + 32 * sizeof(float) + 32 * sizeof(int) + 4 * sizeof(float);
    fps_kernel<<<B, 1024, fps_smem>>>(gt, gtfps);

    // f := 0
    zero_kernel<<<(B * N2 + 255) / 256, 256>>>(f1, f2);

    // EMD1 (output1 vs gt_fps), n = 1024
    {
        dim3 grid(N1 / 128, B);
        size_t sm = (size_t)N1 * 16;
        for (int t = 0; t < MAXITER; t++) {
            lse_kernel<<<grid, 128, sm>>>(gtfps, o1, f1, g1v, N1, eps_p, iters_p, t);
            lse_kernel<<<grid, 128, sm>>>(o1, gtfps, g1v, f1, N1, eps_p, iters_p, t);
        }
        lse_kernel<<<grid, 128, sm>>>(gtfps, o1, f1, g1v, N1, eps_p, iters_p, -1);
        size_t asm_sm = (size_t)N1 * 16 + (size_t)N1 * 4 + 128 * 4;
        assign_kernel<<<grid, 128, asm_sm>>>(o1, gtfps, g1v, e1p, N1);
    }

    // EMD2 (output2 vs gt), n = 4096
    {
        dim3 grid(N2 / 128, B);
        size_t sm = (size_t)N2 * 16;
        for (int t = 0; t < MAXITER; t++) {
            lse_kernel<<<grid, 128, sm>>>(gt, o2, f2, g2v, N2, eps_p, iters_p, t);
            lse_kernel<<<grid, 128, sm>>>(o2, gt, g2v, f2, N2, eps_p, iters_p, t);
        }
        lse_kernel<<<grid, 128, sm>>>(gt, o2, f2, g2v, N2, eps_p, iters_p, -1);
        size_t asm_sm = (size_t)N2 * 16 + (size_t)N2 * 4 + 128 * 4;
        assign_kernel<<<grid, 128, asm_sm>>>(o2, gt, g2v, e2p, N2);
    }

    // Chamfer distances
    {
        size_t sm_o1 = (size_t)N1 * 16 + 128 * 8;
        size_t sm_big = (size_t)N2 * 16 + 128 * 8;
        chamfer_kernel<<<dim3(N2 / 128, B), 128, sm_o1>>>(gt, o1, N2, N1, p11);   // d11
        chamfer_kernel<<<dim3(N1 / 128, B), 128, sm_big>>>(o1, gt, N1, N2, p12);  // d12
        chamfer_kernel<<<dim3(N2 / 128, B), 128, sm_big>>>(gt, o2, N2, N2, p21);  // d21
        chamfer_kernel<<<dim3(N2 / 128, B), 128, sm_big>>>(o2, gt, N2, N2, p22);  // d22
    }

    finalize_kernel<<<1, 32>>>(out);
}

// round 4
// speedup vs baseline: 2.4934x; 2.4934x over previous
#include <cuda_runtime.h>
#include <math.h>

#define B  4
#define N1 1024
#define N2 4096
#define MAXITER 10
#define OUT_SCALARS 61440
#define FULL 0xffffffffu

// ---------------------------------------------------------------------------
// Scratch (device globals; no allocations allowed)
// ---------------------------------------------------------------------------
__device__ float  g_gtfps[B * N1 * 3];
__device__ float  g_f1[B * N1];
__device__ float  g_g1[B * N1];
__device__ float  g_f2[B * N2];
__device__ float  g_g2[B * N2];
__device__ float  g_emdp[320];     // [0,256): emd2 block partials, [256,320): emd1
__device__ float2 g_cdp[832];      // d21 [0,256), d22 [256,512), d11 [512,768), d12 [768,832)
__device__ int    g_default_iters = MAXITER;

// ---------------------------------------------------------------------------
__global__ void zero_kernel(float* f1, float* f2) {
    int i = blockIdx.x * blockDim.x + threadIdx.x;
    if (i < B * N1) f1[i] = 0.0f;
    if (i < B * N2) f2[i] = 0.0f;
}

// ---------------------------------------------------------------------------
// FPS: 1 block of 1024 threads per batch, 1023 sequential argmax steps.
// u32 REDUX argmax (distances are nonneg -> bits monotone), exact first-index
// tiebreak (per-lane ascending strict >, then global min-index among maxima).
// One barrier per step via double-buffered leader array; every warp redoes the
// 32-wide level-2 reduction so no second barrier is needed.
// ---------------------------------------------------------------------------
__global__ __launch_bounds__(1024, 1)
void fps_kernel(const float* __restrict__ gt, float* __restrict__ gtfps) {
    extern __shared__ float smraw_f[];
    float4*   spts = (float4*)smraw_f;            // N2
    unsigned* lum  = (unsigned*)(spts + N2);      // 2*32
    unsigned* lui  = lum + 64;                    // 2*32

    int b = blockIdx.x;
    const float* pts = gt + (size_t)b * N2 * 3;
    int tid = threadIdx.x;

    for (int i = tid; i < N2; i += 1024) {
        float x = pts[3 * i], y = pts[3 * i + 1], z = pts[3 * i + 2];
        spts[i] = make_float4(x, y, z, 0.0f);
    }
    __syncthreads();

    float4 p0 = spts[0];
    float px[4], py[4], pz[4], d[4];
#pragma unroll
    for (int c = 0; c < 4; c++) {
        float4 e = spts[tid + c * 1024];
        px[c] = e.x; py[c] = e.y; pz[c] = e.z;
        float dx = e.x - p0.x, dy = e.y - p0.y, dz = e.z - p0.z;
        d[c] = dx * dx + dy * dy + dz * dz;
    }

    float* outp = gtfps + (size_t)b * N1 * 3;
    if (tid == 0) { outp[0] = p0.x; outp[1] = p0.y; outp[2] = p0.z; }

    int lane = tid & 31, warp = tid >> 5;
    for (int t = 1; t < N1; t++) {
        // local argmax (ascending index, strict > -> first-index tiebreak)
        float bv = d[0]; int bi = tid;
#pragma unroll
        for (int c = 1; c < 4; c++)
            if (d[c] > bv) { bv = d[c]; bi = tid + c * 1024; }

        unsigned ub = __float_as_uint(bv);
        unsigned um = __reduce_max_sync(FULL, ub);
        unsigned cand = (ub == um) ? (unsigned)bi : 0xffffffffu;
        unsigned ui = __reduce_min_sync(FULL, cand);

        int buf = (t & 1) * 32;
        if (lane == 0) { lum[buf + warp] = um; lui[buf + warp] = ui; }
        __syncthreads();

        // all warps redundantly reduce the 32 leaders (no 2nd barrier)
        unsigned vm = lum[buf + lane], vi = lui[buf + lane];
        unsigned gm = __reduce_max_sync(FULL, vm);
        unsigned c2 = (vm == gm) ? vi : 0xffffffffu;
        unsigned gi = __reduce_min_sync(FULL, c2);

        float4 sp = spts[gi];
        if (tid == 0) { outp[3 * t] = sp.x; outp[3 * t + 1] = sp.y; outp[3 * t + 2] = sp.z; }
#pragma unroll
        for (int c = 0; c < 4; c++) {
            float dx = px[c] - sp.x, dy = py[c] - sp.y, dz = pz[c] - sp.z;
            float dd = dx * dx + dy * dy + dz * dz;
            d[c] = fminf(d[c], dd);
        }
    }
}

// ---------------------------------------------------------------------------
// Fused LSE half-step for BOTH problems. Warp handles 8 outputs, lanes split
// the reduction dim (k = lane + 32*it). Tile {x,y,z,(v-||p||^2)/eps} in smem.
// p = fma(ex,cqx, fma(ey,cqy, fma(ez,cqz, w))) with cq = (2/eps)*q  -> 3 FMA.
// ---------------------------------------------------------------------------
template<int NSZ>
__device__ __forceinline__ void lse_block(
    const float* __restrict__ Po, const float* __restrict__ Pr,
    const float* __restrict__ vr, float* __restrict__ vo,
    int outbase, float eps, float inv_eps, float loga, float4* tile)
{
    int tid = threadIdx.x;
    for (int k = tid; k < NSZ; k += 256) {
        float x = Pr[3 * k], y = Pr[3 * k + 1], z = Pr[3 * k + 2];
        float na = x * x + y * y + z * z;
        tile[k] = make_float4(x, y, z, (vr[k] - na) * inv_eps);
    }
    __syncthreads();

    int lane = tid & 31;
    int j0 = outbase + (tid >> 5) * 8;
    float c1 = 2.0f * inv_eps;
    float cqx[8], cqy[8], cqz[8], cj[8], m[8];
#pragma unroll
    for (int o = 0; o < 8; o++) {
        float qx = __ldg(Po + 3 * (j0 + o));
        float qy = __ldg(Po + 3 * (j0 + o) + 1);
        float qz = __ldg(Po + 3 * (j0 + o) + 2);
        cqx[o] = c1 * qx; cqy[o] = c1 * qy; cqz[o] = c1 * qz;
        cj[o] = fmaf(-(qx * qx + qy * qy + qz * qz), inv_eps, loga);
        m[o] = -3.4e38f;
    }

#pragma unroll 2
    for (int it = 0; it < NSZ / 32; ++it) {
        float4 e = tile[it * 32 + lane];
#pragma unroll
        for (int o = 0; o < 8; o++) {
            float p = fmaf(e.x, cqx[o], fmaf(e.y, cqy[o], fmaf(e.z, cqz[o], e.w)));
            m[o] = fmaxf(m[o], p);
        }
    }
#pragma unroll
    for (int o = 0; o < 8; o++)
#pragma unroll
        for (int off = 16; off; off >>= 1)
            m[o] = fmaxf(m[o], __shfl_xor_sync(FULL, m[o], off));

    float s[8], mth[8];
#pragma unroll
    for (int o = 0; o < 8; o++) { s[o] = 0.0f; mth[o] = m[o] - 87.0f; }

#pragma unroll 2
    for (int it = 0; it < NSZ / 32; ++it) {
        float4 e = tile[it * 32 + lane];
#pragma unroll
        for (int o = 0; o < 8; o++) {
            float p = fmaf(e.x, cqx[o], fmaf(e.y, cqy[o], fmaf(e.z, cqz[o], e.w)));
            if (p > mth[o]) s[o] += __expf(p - m[o]);
        }
    }
#pragma unroll
    for (int o = 0; o < 8; o++)
#pragma unroll
        for (int off = 16; off; off >>= 1)
            s[o] += __shfl_xor_sync(FULL, s[o], off);

#pragma unroll
    for (int o = 0; o < 8; o++)
        if (lane == o)
            vo[j0 + o] = -eps * (m[o] + cj[o] + logf(s[o]));
}

__global__ __launch_bounds__(256)
void lse_fused(const float* Po1, const float* Pr1, const float* vr1, float* vo1,
               const float* Po2, const float* Pr2, const float* vr2, float* vo2,
               const float* __restrict__ eps_p, const int* __restrict__ iters_p, int t)
{
    if (t >= 0 && t >= __ldg(iters_p)) return;
    extern __shared__ float4 tile[];
    float eps = __ldg(eps_p), inv = 1.0f / eps;
    int bx = blockIdx.x;
    if (bx < 256) {
        int b = bx >> 6;
        lse_block<N2>(Po2 + (size_t)b * N2 * 3, Pr2 + (size_t)b * N2 * 3,
                      vr2 + (size_t)b * N2, vo2 + (size_t)b * N2,
                      (bx & 63) * 64, eps, inv, -8.3177661667193436f, tile);
    } else {
        int g = bx - 256, b = g >> 4;
        lse_block<N1>(Po1 + (size_t)b * N1 * 3, Pr1 + (size_t)b * N1 * 3,
                      vr1 + (size_t)b * N1, vo1 + (size_t)b * N1,
                      (g & 15) * 64, eps, inv, -6.9314718055994531f, tile);
    }
}

// ---------------------------------------------------------------------------
// Fused assignment: per x-point argmax_j (g_j - C_ij) (f_i constant), exact
// first-index tiebreak via sortable-uint REDUX. val = 2dot + (g - ||y||^2);
// the -na per-output constant drops out of the argmax. C at winner recovered
// as na + g_k - val. Block writes sum(sqrt(C)) over its 64 outputs.
// ---------------------------------------------------------------------------
__device__ __forceinline__ unsigned sortkey(float f) {
    unsigned u = __float_as_uint(f);
    return ((int)u < 0) ? ~u : (u | 0x80000000u);
}

template<int NSZ>
__device__ __forceinline__ void assign_block(
    const float* __restrict__ Px, const float* __restrict__ Py,
    const float* __restrict__ gv, float* __restrict__ partial,
    int outbase, int pidx, char* smraw)
{
    float4* tile = (float4*)smraw;          // NSZ: {x,y,z, g-ny}
    float*  garr = (float*)(tile + NSZ);    // NSZ: g
    float*  wred = garr + NSZ;              // 8
    int tid = threadIdx.x;
    for (int k = tid; k < NSZ; k += 256) {
        float x = Py[3 * k], y = Py[3 * k + 1], z = Py[3 * k + 2];
        float ny = x * x + y * y + z * z;
        float gk = gv[k];
        garr[k] = gk;
        tile[k] = make_float4(x, y, z, gk - ny);
    }
    __syncthreads();

    int lane = tid & 31, w = tid >> 5;
    int j0 = outbase + w * 8;
    float c2x[8], c2y[8], c2z[8], na[8], bv[8]; int bi[8];
#pragma unroll
    for (int o = 0; o < 8; o++) {
        float qx = __ldg(Px + 3 * (j0 + o));
        float qy = __ldg(Px + 3 * (j0 + o) + 1);
        float qz = __ldg(Px + 3 * (j0 + o) + 2);
        c2x[o] = 2.0f * qx; c2y[o] = 2.0f * qy; c2z[o] = 2.0f * qz;
        na[o] = qx * qx + qy * qy + qz * qz;
        bv[o] = -3.4e38f; bi[o] = 0;
    }
#pragma unroll 2
    for (int it = 0; it < NSZ / 32; ++it) {
        int k = it * 32 + lane;
        float4 e = tile[k];
#pragma unroll
        for (int o = 0; o < 8; o++) {
            float v = fmaf(e.x, c2x[o], fmaf(e.y, c2y[o], fmaf(e.z, c2z[o], e.w)));
            if (v > bv[o]) { bv[o] = v; bi[o] = k; }
        }
    }
    float acc = 0.0f;
#pragma unroll
    for (int o = 0; o < 8; o++) {
        unsigned key  = sortkey(bv[o]);
        unsigned kmax = __reduce_max_sync(FULL, key);
        unsigned cand = (key == kmax) ? (unsigned)bi[o] : 0xffffffffu;
        unsigned imin = __reduce_min_sync(FULL, cand);
        if (key == kmax && (unsigned)bi[o] == imin) {
            float C = fmaxf(na[o] + garr[bi[o]] - bv[o], 0.0f);
            acc += sqrtf(C);
        }
    }
#pragma unroll
    for (int off = 16; off; off >>= 1) acc += __shfl_xor_sync(FULL, acc, off);
    if (lane == 0) wred[w] = acc;
    __syncthreads();
    if (tid == 0) {
        float sum = 0.0f;
        for (int i = 0; i < 8; i++) sum += wred[i];
        partial[pidx] = sum;
    }
}

__global__ __launch_bounds__(256)
void assign_fused(const float* Px1, const float* Py1, const float* g1v,
                  const float* Px2, const float* Py2, const float* g2v,
                  float* partial)
{
    extern __shared__ char smraw_a[];
    int bx = blockIdx.x;
    if (bx < 256) {
        int b = bx >> 6;
        assign_block<N2>(Px2 + (size_t)b * N2 * 3, Py2 + (size_t)b * N2 * 3,
                         g2v + (size_t)b * N2, partial, (bx & 63) * 64, bx, smraw_a);
    } else {
        int g = bx - 256, b = g >> 4;
        assign_block<N1>(Px1 + (size_t)b * N1 * 3, Py1 + (size_t)b * N1 * 3,
                         g1v + (size_t)b * N1, partial, (g & 15) * 64, bx, smraw_a);
    }
}

// ---------------------------------------------------------------------------
// Fused chamfer: all 4 directions in one launch. min over reduce side of
// (||y||^2 - 2dot); +na and clamp applied after the min (monotone shift).
// ---------------------------------------------------------------------------
template<int NSZ>
__device__ __forceinline__ void chamfer_block(
    const float* __restrict__ Pa, const float* __restrict__ Pb,
    float2* __restrict__ partial, int outbase, int pidx, char* smraw)
{
    float4* tile = (float4*)smraw;            // NSZ {x,y,z,ny}
    float2* wred = (float2*)(tile + NSZ);     // 8
    int tid = threadIdx.x;
    for (int k = tid; k < NSZ; k += 256) {
        float x = Pb[3 * k], y = Pb[3 * k + 1], z = Pb[3 * k + 2];
        tile[k] = make_float4(x, y, z, x * x + y * y + z * z);
    }
    __syncthreads();

    int lane = tid & 31, w = tid >> 5;
    int j0 = outbase + w * 8;
    float m2x[8], m2y[8], m2z[8], na[8], mn[8];
#pragma unroll
    for (int o = 0; o < 8; o++) {
        float qx = __ldg(Pa + 3 * (j0 + o));
        float qy = __ldg(Pa + 3 * (j0 + o) + 1);
        float qz = __ldg(Pa + 3 * (j0 + o) + 2);
        m2x[o] = -2.0f * qx; m2y[o] = -2.0f * qy; m2z[o] = -2.0f * qz;
        na[o] = qx * qx + qy * qy + qz * qz;
        mn[o] = 3.4e38f;
    }
#pragma unroll 2
    for (int it = 0; it < NSZ / 32; ++it) {
        float4 e = tile[it * 32 + lane];
#pragma unroll
        for (int o = 0; o < 8; o++) {
            float v = fmaf(e.x, m2x[o], fmaf(e.y, m2y[o], fmaf(e.z, m2z[o], e.w)));
            mn[o] = fminf(mn[o], v);
        }
    }
#pragma unroll
    for (int o = 0; o < 8; o++)
#pragma unroll
        for (int off = 16; off; off >>= 1)
            mn[o] = fminf(mn[o], __shfl_xor_sync(FULL, mn[o], off));

    if (lane == 0) {
        float ssq = 0.0f, sd = 0.0f;
#pragma unroll
        for (int o = 0; o < 8; o++) {
            float d = fmaxf(mn[o] + na[o], 0.0f);
            ssq += sqrtf(d); sd += d;
        }
        wred[w] = make_float2(ssq, sd);
    }
    __syncthreads();
    if (tid == 0) {
        float a = 0.0f, bm = 0.0f;
        for (int i = 0; i < 8; i++) { a += wred[i].x; bm += wred[i].y; }
        partial[pidx] = make_float2(a, bm);
    }
}

__global__ __launch_bounds__(256)
void chamfer_fused(const float* o1, const float* o2, const float* gt,
                   float2* partial)
{
    extern __shared__ char smraw_c[];
    int bx = blockIdx.x;
    if (bx < 256) {               // d21: a=gt (4096 outs), reduce o2 (4096)
        int b = bx >> 6;
        chamfer_block<N2>(gt + (size_t)b * N2 * 3, o2 + (size_t)b * N2 * 3,
                          partial, (bx & 63) * 64, bx, smraw_c);
    } else if (bx < 512) {        // d22: a=o2, reduce gt
        int g = bx - 256, b = g >> 6;
        chamfer_block<N2>(o2 + (size_t)b * N2 * 3, gt + (size_t)b * N2 * 3,
                          partial, (g & 63) * 64, bx, smraw_c);
    } else if (bx < 768) {        // d11: a=gt (4096 outs), reduce o1 (1024)
        int g = bx - 512, b = g >> 6;
        chamfer_block<N1>(gt + (size_t)b * N2 * 3, o1 + (size_t)b * N1 * 3,
                          partial, (g & 63) * 64, bx, smraw_c);
    } else {                      // d12: a=o1 (1024 outs), reduce gt (4096)
        int g = bx - 768, b = g >> 4;
        chamfer_block<N2>(o1 + (size_t)b * N1 * 3, gt + (size_t)b * N2 * 3,
                          partial, (g & 15) * 64, bx, smraw_c);
    }
}

// ---------------------------------------------------------------------------
__global__ void finalize_kernel(float* __restrict__ out) {
    int b = threadIdx.x;
    if (b >= B) return;

    float s = 0.0f;
    for (int i = 0; i < 16; i++) s += g_emdp[256 + b * 16 + i];
    out[OUT_SCALARS + 0 + b] = s / (float)N1;                       // emd1

    s = 0.0f;
    for (int i = 0; i < 64; i++) s += g_emdp[b * 64 + i];
    out[OUT_SCALARS + 4 + b] = s / (float)N2;                       // emd2

    float ss21 = 0, sd21 = 0, ss22 = 0, sd22 = 0;
    float ss11 = 0, sd11 = 0, ss12 = 0, sd12 = 0;
    for (int i = 0; i < 64; i++) { float2 v = g_cdp[        b * 64 + i]; ss21 += v.x; sd21 += v.y; }
    for (int i = 0; i < 64; i++) { float2 v = g_cdp[256 +   b * 64 + i]; ss22 += v.x; sd22 += v.y; }
    for (int i = 0; i < 64; i++) { float2 v = g_cdp[512 +   b * 64 + i]; ss11 += v.x; sd11 += v.y; }
    for (int i = 0; i < 16; i++) { float2 v = g_cdp[768 +   b * 16 + i]; ss12 += v.x; sd12 += v.y; }

    out[OUT_SCALARS + 8  + b] = (ss11 / (float)N2 + ss12 / (float)N1) * 0.5f;  // cd_p1
    out[OUT_SCALARS + 12 + b] = (ss21 / (float)N2 + ss22 / (float)N2) * 0.5f;  // cd_p2
    out[OUT_SCALARS + 16 + b] =  sd11 / (float)N2 + sd12 / (float)N1;          // cd_t1
    out[OUT_SCALARS + 20 + b] =  sd21 / (float)N2 + sd22 / (float)N2;          // cd_t2
}

// ---------------------------------------------------------------------------
extern "C" void kernel_launch(void* const* d_in, const int* in_sizes, int n_in,
                              void* d_out, int out_size) {
    const float* o1    = (const float*)d_in[0];
    const float* o2    = (const float*)d_in[1];
    const float* gt    = (const float*)d_in[2];
    const float* eps_p = (const float*)d_in[3];
    float* out = (float*)d_out;

    float *gtfps, *f1, *g1v, *f2, *g2v, *emdp;
    float2* cdp;
    int* def_iters;
    cudaGetSymbolAddress((void**)&gtfps, g_gtfps);
    cudaGetSymbolAddress((void**)&f1, g_f1);
    cudaGetSymbolAddress((void**)&g1v, g_g1);
    cudaGetSymbolAddress((void**)&f2, g_f2);
    cudaGetSymbolAddress((void**)&g2v, g_g2);
    cudaGetSymbolAddress((void**)&emdp, g_emdp);
    cudaGetSymbolAddress((void**)&cdp, g_cdp);
    cudaGetSymbolAddress((void**)&def_iters, g_default_iters);

    const int* iters_p = (n_in > 4) ? (const int*)d_in[4] : def_iters;

    size_t fps_smem    = (size_t)N2 * 16 + 128 * 4;          // 66048
    size_t lse_smem    = (size_t)N2 * 16;                    // 65536
    size_t assign_smem = (size_t)N2 * 16 + (size_t)N2 * 4 + 8 * 4;   // 81952
    size_t cham_smem   = (size_t)N2 * 16 + 8 * 8;            // 65600

    cudaFuncSetAttribute(fps_kernel,    cudaFuncAttributeMaxDynamicSharedMemorySize, (int)fps_smem);
    cudaFuncSetAttribute(lse_fused,     cudaFuncAttributeMaxDynamicSharedMemorySize, (int)lse_smem);
    cudaFuncSetAttribute(assign_fused,  cudaFuncAttributeMaxDynamicSharedMemorySize, (int)assign_smem);
    cudaFuncSetAttribute(chamfer_fused, cudaFuncAttributeMaxDynamicSharedMemorySize, (int)cham_smem);

    // Passthrough copies
    cudaMemcpyAsync(out, o1, (size_t)B * N1 * 3 * sizeof(float), cudaMemcpyDeviceToDevice);
    cudaMemcpyAsync(out + B * N1 * 3, o2, (size_t)B * N2 * 3 * sizeof(float), cudaMemcpyDeviceToDevice);

    fps_kernel<<<B, 1024, fps_smem>>>(gt, gtfps);
    zero_kernel<<<(B * N2 + 255) / 256, 256>>>(f1, f2);

    // Sinkhorn: 10 iterations (g-step, f-step) + final g, both problems fused
    for (int t = 0; t < MAXITER; t++) {
        lse_fused<<<320, 256, lse_smem>>>(gtfps, o1, f1, g1v,  gt, o2, f2, g2v, eps_p, iters_p, t);
        lse_fused<<<320, 256, lse_smem>>>(o1, gtfps, g1v, f1,  o2, gt, g2v, f2, eps_p, iters_p, t);
    }
    lse_fused<<<320, 256, lse_smem>>>(gtfps, o1, f1, g1v,  gt, o2, f2, g2v, eps_p, iters_p, -1);

    assign_fused<<<320, 256, assign_smem>>>(o1, gtfps, g1v, o2, gt, g2v, emdp);
    chamfer_fused<<<832, 256, cham_smem>>>(o1, o2, gt, cdp);
    finalize_kernel<<<1, 32>>>(out);
}

// round 6
// speedup vs baseline: 3.5463x; 1.4223x over previous
#include <cuda_runtime.h>
#include <math.h>

#define B  4
#define N1 1024
#define N2 4096
#define MAXITER 10
#define OUT_SCALARS 61440
#define FULL 0xffffffffu

#define LN2F   0.69314718055994531f
#define LOG2EF 1.44269504088896340f

// ---------------------------------------------------------------------------
// Scratch (device globals; no allocations allowed)
// ---------------------------------------------------------------------------
__device__ float  g_gtfps[B * N1 * 3];
__device__ float  g_f1[B * N1];
__device__ float  g_g1[B * N1];
__device__ float  g_f2[B * N2];
__device__ float  g_g2[B * N2];
__device__ float  g_emdp[320];     // [0,256): emd2 block partials, [256,320): emd1
__device__ float2 g_cdp[832];      // d21 [0,256), d22 [256,512), d11 [512,768), d12 [768,832)
__device__ int    g_default_iters = MAXITER;

// ---------------------------------------------------------------------------
// Packed f32x2 helpers (sm_103a): FFMA2/FADD2 only reachable via PTX.
// ---------------------------------------------------------------------------
typedef unsigned long long u64;
__device__ __forceinline__ u64 f2pk(float lo, float hi) {
    u64 r; asm("mov.b64 %0, {%1, %2};" : "=l"(r) : "f"(lo), "f"(hi)); return r;
}
__device__ __forceinline__ u64 dup2(float v) {
    u64 r; asm("mov.b64 %0, {%1, %1};" : "=l"(r) : "f"(v)); return r;
}
__device__ __forceinline__ void unpk(u64 v, float& lo, float& hi) {
    asm("mov.b64 {%0, %1}, %2;" : "=f"(lo), "=f"(hi) : "l"(v));
}
__device__ __forceinline__ u64 ffma2(u64 a, u64 b, u64 c) {
    u64 d; asm("fma.rn.f32x2 %0, %1, %2, %3;" : "=l"(d) : "l"(a), "l"(b), "l"(c)); return d;
}
__device__ __forceinline__ u64 fadd2(u64 a, u64 b) {
    u64 d; asm("add.rn.f32x2 %0, %1, %2;" : "=l"(d) : "l"(a), "l"(b)); return d;
}
__device__ __forceinline__ float ex2f(float x) {
    float r; asm("ex2.approx.ftz.f32 %0, %1;" : "=f"(r) : "f"(x)); return r;
}
__device__ __forceinline__ float lg2f(float x) {
    float r; asm("lg2.approx.ftz.f32 %0, %1;" : "=f"(r) : "f"(x)); return r;
}

// ---------------------------------------------------------------------------
// FPS: 1 block of 1024 threads per batch, 1023 sequential argmax steps.
// u32 REDUX argmax (nonneg distances -> bits monotone), exact first-index
// tiebreak. One barrier per step (double-buffered leaders + redundant L2).
// ---------------------------------------------------------------------------
__global__ __launch_bounds__(1024, 1)
void fps_kernel(const float* __restrict__ gt, float* __restrict__ gtfps) {
    extern __shared__ float smraw_f[];
    float4*   spts = (float4*)smraw_f;            // N2
    unsigned* lum  = (unsigned*)(spts + N2);      // 2*32
    unsigned* lui  = lum + 64;                    // 2*32

    int b = blockIdx.x;
    const float* pts = gt + (size_t)b * N2 * 3;
    int tid = threadIdx.x;

    for (int i = tid; i < N2; i += 1024) {
        float x = pts[3 * i], y = pts[3 * i + 1], z = pts[3 * i + 2];
        spts[i] = make_float4(x, y, z, 0.0f);
    }
    __syncthreads();

    float4 p0 = spts[0];
    float px[4], py[4], pz[4], d[4];
#pragma unroll
    for (int c = 0; c < 4; c++) {
        float4 e = spts[tid + c * 1024];
        px[c] = e.x; py[c] = e.y; pz[c] = e.z;
        float dx = e.x - p0.x, dy = e.y - p0.y, dz = e.z - p0.z;
        d[c] = dx * dx + dy * dy + dz * dz;
    }

    float* outp = gtfps + (size_t)b * N1 * 3;
    if (tid == 0) { outp[0] = p0.x; outp[1] = p0.y; outp[2] = p0.z; }

    int lane = tid & 31, warp = tid >> 5;
    for (int t = 1; t < N1; t++) {
        float bv = d[0]; int bi = tid;
#pragma unroll
        for (int c = 1; c < 4; c++)
            if (d[c] > bv) { bv = d[c]; bi = tid + c * 1024; }

        unsigned ub = __float_as_uint(bv);
        unsigned um = __reduce_max_sync(FULL, ub);
        unsigned cand = (ub == um) ? (unsigned)bi : 0xffffffffu;
        unsigned ui = __reduce_min_sync(FULL, cand);

        int buf = (t & 1) * 32;
        if (lane == 0) { lum[buf + warp] = um; lui[buf + warp] = ui; }
        __syncthreads();

        unsigned vm = lum[buf + lane], vi = lui[buf + lane];
        unsigned gm = __reduce_max_sync(FULL, vm);
        unsigned c2 = (vm == gm) ? vi : 0xffffffffu;
        unsigned gi = __reduce_min_sync(FULL, c2);

        float4 sp = spts[gi];
        if (tid == 0) { outp[3 * t] = sp.x; outp[3 * t + 1] = sp.y; outp[3 * t + 2] = sp.z; }
#pragma unroll
        for (int c = 0; c < 4; c++) {
            float dx = px[c] - sp.x, dy = py[c] - sp.y, dz = pz[c] - sp.z;
            float dd = dx * dx + dy * dy + dz * dz;
            d[c] = fminf(d[c], dd);
        }
    }
}

// ---------------------------------------------------------------------------
// LSE half-step, base-2 formulation, packed f32x2, branchless pass 2.
// Tile: {x, y, z, (v - ||p||^2) * log2e/eps}. cq = (2 log2e/eps) * q.
// p2 = dot-chain in log2 units; LSE_nat = ln2*(m2 + log2(sum 2^(p2-m2))).
// Warp = 8 outputs (4 packed pairs), lanes split K.
// ---------------------------------------------------------------------------
template<int NSZ>
__device__ __forceinline__ void lse_block(
    const float* __restrict__ Po, const float* __restrict__ Pr,
    const float* __restrict__ vr, float* __restrict__ vo,
    int outbase, float eps, float inv_eps, float loga, float4* tile, int zerov)
{
    int tid = threadIdx.x;
    float scal = inv_eps * LOG2EF;
    for (int k = tid; k < NSZ; k += 256) {
        float x = Pr[3 * k], y = Pr[3 * k + 1], z = Pr[3 * k + 2];
        float na = x * x + y * y + z * z;
        float v = zerov ? 0.0f : vr[k];
        tile[k] = make_float4(x, y, z, (v - na) * scal);
    }
    __syncthreads();

    int lane = tid & 31;
    int j0 = outbase + (tid >> 5) * 8;
    float c1 = 2.0f * scal;
    u64 cqx2[4], cqy2[4], cqz2[4];
#pragma unroll
    for (int p = 0; p < 4; p++) {
        int ja = j0 + 2 * p, jb = ja + 1;
        cqx2[p] = f2pk(c1 * __ldg(Po + 3 * ja),     c1 * __ldg(Po + 3 * jb));
        cqy2[p] = f2pk(c1 * __ldg(Po + 3 * ja + 1), c1 * __ldg(Po + 3 * jb + 1));
        cqz2[p] = f2pk(c1 * __ldg(Po + 3 * ja + 2), c1 * __ldg(Po + 3 * jb + 2));
    }

    // pass 1: max of p2
    float m[8];
#pragma unroll
    for (int o = 0; o < 8; o++) m[o] = -3.4e38f;
#pragma unroll 2
    for (int it = 0; it < NSZ / 32; ++it) {
        float4 e = tile[it * 32 + lane];
        u64 xx = dup2(e.x), yy = dup2(e.y), zz = dup2(e.z), ww = dup2(e.w);
#pragma unroll
        for (int p = 0; p < 4; p++) {
            u64 t = ffma2(xx, cqx2[p], ffma2(yy, cqy2[p], ffma2(zz, cqz2[p], ww)));
            float lo, hi; unpk(t, lo, hi);
            m[2 * p]     = fmaxf(m[2 * p], lo);
            m[2 * p + 1] = fmaxf(m[2 * p + 1], hi);
        }
    }
#pragma unroll
    for (int o = 0; o < 8; o++)
#pragma unroll
        for (int off = 16; off; off >>= 1)
            m[o] = fmaxf(m[o], __shfl_xor_sync(FULL, m[o], off));

    u64 nm2[4];
#pragma unroll
    for (int p = 0; p < 4; p++) nm2[p] = f2pk(-m[2 * p], -m[2 * p + 1]);

    // pass 2: branchless sum of 2^(p2 - m2)
    float s[8];
#pragma unroll
    for (int o = 0; o < 8; o++) s[o] = 0.0f;
#pragma unroll 2
    for (int it = 0; it < NSZ / 32; ++it) {
        float4 e = tile[it * 32 + lane];
        u64 xx = dup2(e.x), yy = dup2(e.y), zz = dup2(e.z), ww = dup2(e.w);
#pragma unroll
        for (int p = 0; p < 4; p++) {
            u64 t = ffma2(xx, cqx2[p], ffma2(yy, cqy2[p], ffma2(zz, cqz2[p], ww)));
            t = fadd2(t, nm2[p]);
            float lo, hi; unpk(t, lo, hi);
            s[2 * p]     += ex2f(lo);
            s[2 * p + 1] += ex2f(hi);
        }
    }
#pragma unroll
    for (int o = 0; o < 8; o++)
#pragma unroll
        for (int off = 16; off; off >>= 1)
            s[o] += __shfl_xor_sync(FULL, s[o], off);

#pragma unroll
    for (int o = 0; o < 8; o++)
        if (lane == o) {
            float qx = __ldg(Po + 3 * (j0 + o));
            float qy = __ldg(Po + 3 * (j0 + o) + 1);
            float qz = __ldg(Po + 3 * (j0 + o) + 2);
            float cj = fmaf(-(qx * qx + qy * qy + qz * qz), inv_eps, loga);
            vo[j0 + o] = -eps * (LN2F * (m[o] + lg2f(s[o])) + cj);
        }
}

// zmode: 0 = read vr; 1 = treat vr as zero; 2 = zero iff *iters <= 0
__global__ __launch_bounds__(256)
void lse_fused(const float* Po1, const float* Pr1, const float* vr1, float* vo1,
               const float* Po2, const float* Pr2, const float* vr2, float* vo2,
               const float* __restrict__ eps_p, const int* __restrict__ iters_p,
               int t, int zmode)
{
    int iters = __ldg(iters_p);
    if (t >= 0 && t >= iters) return;
    int zerov = (zmode == 1) || (zmode == 2 && iters <= 0);
    extern __shared__ float4 tile[];
    float eps = __ldg(eps_p), inv = 1.0f / eps;
    int bx = blockIdx.x;
    if (bx < 256) {
        int b = bx >> 6;
        lse_block<N2>(Po2 + (size_t)b * N2 * 3, Pr2 + (size_t)b * N2 * 3,
                      vr2 + (size_t)b * N2, vo2 + (size_t)b * N2,
                      (bx & 63) * 64, eps, inv, -8.3177661667193436f, tile, zerov);
    } else {
        int g = bx - 256, b = g >> 4;
        lse_block<N1>(Po1 + (size_t)b * N1 * 3, Pr1 + (size_t)b * N1 * 3,
                      vr1 + (size_t)b * N1, vo1 + (size_t)b * N1,
                      (g & 15) * 64, eps, inv, -6.9314718055994531f, tile, zerov);
    }
}

// ---------------------------------------------------------------------------
// Fused assignment (exact first-index argmax of g_j - C_ij, then sum sqrt(C))
// ---------------------------------------------------------------------------
__device__ __forceinline__ unsigned sortkey(float f) {
    unsigned u = __float_as_uint(f);
    return ((int)u < 0) ? ~u : (u | 0x80000000u);
}

template<int NSZ>
__device__ __forceinline__ void assign_block(
    const float* __restrict__ Px, const float* __restrict__ Py,
    const float* __restrict__ gv, float* __restrict__ partial,
    int outbase, int pidx, char* smraw)
{
    float4* tile = (float4*)smraw;          // NSZ: {x,y,z, g-ny}
    float*  garr = (float*)(tile + NSZ);    // NSZ: g
    float*  wred = garr + NSZ;              // 8
    int tid = threadIdx.x;
    for (int k = tid; k < NSZ; k += 256) {
        float x = Py[3 * k], y = Py[3 * k + 1], z = Py[3 * k + 2];
        float ny = x * x + y * y + z * z;
        float gk = gv[k];
        garr[k] = gk;
        tile[k] = make_float4(x, y, z, gk - ny);
    }
    __syncthreads();

    int lane = tid & 31, w = tid >> 5;
    int j0 = outbase + w * 8;
    float c2x[8], c2y[8], c2z[8], na[8], bv[8]; int bi[8];
#pragma unroll
    for (int o = 0; o < 8; o++) {
        float qx = __ldg(Px + 3 * (j0 + o));
        float qy = __ldg(Px + 3 * (j0 + o) + 1);
        float qz = __ldg(Px + 3 * (j0 + o) + 2);
        c2x[o] = 2.0f * qx; c2y[o] = 2.0f * qy; c2z[o] = 2.0f * qz;
        na[o] = qx * qx + qy * qy + qz * qz;
        bv[o] = -3.4e38f; bi[o] = 0;
    }
#pragma unroll 2
    for (int it = 0; it < NSZ / 32; ++it) {
        int k = it * 32 + lane;
        float4 e = tile[k];
#pragma unroll
        for (int o = 0; o < 8; o++) {
            float v = fmaf(e.x, c2x[o], fmaf(e.y, c2y[o], fmaf(e.z, c2z[o], e.w)));
            if (v > bv[o]) { bv[o] = v; bi[o] = k; }
        }
    }
    float acc = 0.0f;
#pragma unroll
    for (int o = 0; o < 8; o++) {
        unsigned key  = sortkey(bv[o]);
        unsigned kmax = __reduce_max_sync(FULL, key);
        unsigned cand = (key == kmax) ? (unsigned)bi[o] : 0xffffffffu;
        unsigned imin = __reduce_min_sync(FULL, cand);
        if (key == kmax && (unsigned)bi[o] == imin) {
            float C = fmaxf(na[o] + garr[bi[o]] - bv[o], 0.0f);
            acc += sqrtf(C);
        }
    }
#pragma unroll
    for (int off = 16; off; off >>= 1) acc += __shfl_xor_sync(FULL, acc, off);
    if (lane == 0) wred[w] = acc;
    __syncthreads();
    if (tid == 0) {
        float sum = 0.0f;
        for (int i = 0; i < 8; i++) sum += wred[i];
        partial[pidx] = sum;
    }
}

__global__ __launch_bounds__(256)
void assign_fused(const float* Px1, const float* Py1, const float* g1v,
                  const float* Px2, const float* Py2, const float* g2v,
                  float* partial)
{
    extern __shared__ char smraw_a[];
    int bx = blockIdx.x;
    if (bx < 256) {
        int b = bx >> 6;
        assign_block<N2>(Px2 + (size_t)b * N2 * 3, Py2 + (size_t)b * N2 * 3,
                         g2v + (size_t)b * N2, partial, (bx & 63) * 64, bx, smraw_a);
    } else {
        int g = bx - 256, b = g >> 4;
        assign_block<N1>(Px1 + (size_t)b * N1 * 3, Py1 + (size_t)b * N1 * 3,
                         g1v + (size_t)b * N1, partial, (g & 15) * 64, bx, smraw_a);
    }
}

// ---------------------------------------------------------------------------
// Fused chamfer (packed f32x2): min over reduce side of (||y||^2 - 2dot);
// +na and clamp applied after the min.
// ---------------------------------------------------------------------------
template<int NSZ>
__device__ __forceinline__ void chamfer_block(
    const float* __restrict__ Pa, const float* __restrict__ Pb,
    float2* __restrict__ partial, int outbase, int pidx, char* smraw)
{
    float4* tile = (float4*)smraw;            // NSZ {x,y,z,ny}
    float2* wred = (float2*)(tile + NSZ);     // 8
    int tid = threadIdx.x;
    for (int k = tid; k < NSZ; k += 256) {
        float x = Pb[3 * k], y = Pb[3 * k + 1], z = Pb[3 * k + 2];
        tile[k] = make_float4(x, y, z, x * x + y * y + z * z);
    }
    __syncthreads();

    int lane = tid & 31, w = tid >> 5;
    int j0 = outbase + w * 8;
    u64 mx2[4], my2[4], mz2[4];
    float na[8], mn[8];
#pragma unroll
    for (int p = 0; p < 4; p++) {
        int ja = j0 + 2 * p, jb = ja + 1;
        float ax = __ldg(Pa + 3 * ja),     bxq = __ldg(Pa + 3 * jb);
        float ay = __ldg(Pa + 3 * ja + 1), by = __ldg(Pa + 3 * jb + 1);
        float az = __ldg(Pa + 3 * ja + 2), bz = __ldg(Pa + 3 * jb + 2);
        mx2[p] = f2pk(-2.0f * ax, -2.0f * bxq);
        my2[p] = f2pk(-2.0f * ay, -2.0f * by);
        mz2[p] = f2pk(-2.0f * az, -2.0f * bz);
        na[2 * p]     = ax * ax + ay * ay + az * az;
        na[2 * p + 1] = bxq * bxq + by * by + bz * bz;
        mn[2 * p] = 3.4e38f; mn[2 * p + 1] = 3.4e38f;
    }
#pragma unroll 2
    for (int it = 0; it < NSZ / 32; ++it) {
        float4 e = tile[it * 32 + lane];
        u64 xx = dup2(e.x), yy = dup2(e.y), zz = dup2(e.z), ww = dup2(e.w);
#pragma unroll
        for (int p = 0; p < 4; p++) {
            u64 t = ffma2(xx, mx2[p], ffma2(yy, my2[p], ffma2(zz, mz2[p], ww)));
            float lo, hi; unpk(t, lo, hi);
            mn[2 * p]     = fminf(mn[2 * p], lo);
            mn[2 * p + 1] = fminf(mn[2 * p + 1], hi);
        }
    }
#pragma unroll
    for (int o = 0; o < 8; o++)
#pragma unroll
        for (int off = 16; off; off >>= 1)
            mn[o] = fminf(mn[o], __shfl_xor_sync(FULL, mn[o], off));

    if (lane == 0) {
        float ssq = 0.0f, sd = 0.0f;
#pragma unroll
        for (int o = 0; o < 8; o++) {
            float d = fmaxf(mn[o] + na[o], 0.0f);
            ssq += sqrtf(d); sd += d;
        }
        wred[w] = make_float2(ssq, sd);
    }
    __syncthreads();
    if (tid == 0) {
        float a = 0.0f, bm = 0.0f;
        for (int i = 0; i < 8; i++) { a += wred[i].x; bm += wred[i].y; }
        partial[pidx] = make_float2(a, bm);
    }
}

__global__ __launch_bounds__(256)
void chamfer_fused(const float* o1, const float* o2, const float* gt,
                   float2* partial)
{
    extern __shared__ char smraw_c[];
    int bx = blockIdx.x;
    if (bx < 256) {               // d21: a=gt (4096 outs), reduce o2 (4096)
        int b = bx >> 6;
        chamfer_block<N2>(gt + (size_t)b * N2 * 3, o2 + (size_t)b * N2 * 3,
                          partial, (bx & 63) * 64, bx, smraw_c);
    } else if (bx < 512) {        // d22: a=o2, reduce gt
        int g = bx - 256, b = g >> 6;
        chamfer_block<N2>(o2 + (size_t)b * N2 * 3, gt + (size_t)b * N2 * 3,
                          partial, (g & 63) * 64, bx, smraw_c);
    } else if (bx < 768) {        // d11: a=gt (4096 outs), reduce o1 (1024)
        int g = bx - 512, b = g >> 6;
        chamfer_block<N1>(gt + (size_t)b * N2 * 3, o1 + (size_t)b * N1 * 3,
                          partial, (g & 63) * 64, bx, smraw_c);
    } else {                      // d12: a=o1 (1024 outs), reduce gt (4096)
        int g = bx - 768, b = g >> 4;
        chamfer_block<N2>(o1 + (size_t)b * N1 * 3, gt + (size_t)b * N2 * 3,
                          partial, (g & 15) * 64, bx, smraw_c);
    }
}

// ---------------------------------------------------------------------------
__global__ void finalize_kernel(float* __restrict__ out) {
    int b = threadIdx.x;
    if (b >= B) return;

    float s = 0.0f;
    for (int i = 0; i < 16; i++) s += g_emdp[256 + b * 16 + i];
    out[OUT_SCALARS + 0 + b] = s / (float)N1;                       // emd1

    s = 0.0f;
    for (int i = 0; i < 64; i++) s += g_emdp[b * 64 + i];
    out[OUT_SCALARS + 4 + b] = s / (float)N2;                       // emd2

    float ss21 = 0, sd21 = 0, ss22 = 0, sd22 = 0;
    float ss11 = 0, sd11 = 0, ss12 = 0, sd12 = 0;
    for (int i = 0; i < 64; i++) { float2 v = g_cdp[      b * 64 + i]; ss21 += v.x; sd21 += v.y; }
    for (int i = 0; i < 64; i++) { float2 v = g_cdp[256 + b * 64 + i]; ss22 += v.x; sd22 += v.y; }
    for (int i = 0; i < 64; i++) { float2 v = g_cdp[512 + b * 64 + i]; ss11 += v.x; sd11 += v.y; }
    for (int i = 0; i < 16; i++) { float2 v = g_cdp[768 + b * 16 + i]; ss12 += v.x; sd12 += v.y; }

    out[OUT_SCALARS + 8  + b] = (ss11 / (float)N2 + ss12 / (float)N1) * 0.5f;  // cd_p1
    out[OUT_SCALARS + 12 + b] = (ss21 / (float)N2 + ss22 / (float)N2) * 0.5f;  // cd_p2
    out[OUT_SCALARS + 16 + b] =  sd11 / (float)N2 + sd12 / (float)N1;          // cd_t1
    out[OUT_SCALARS + 20 + b] =  sd21 / (float)N2 + sd22 / (float)N2;          // cd_t2
}

// ---------------------------------------------------------------------------
extern "C" void kernel_launch(void* const* d_in, const int* in_sizes, int n_in,
                              void* d_out, int out_size) {
    const float* o1    = (const float*)d_in[0];
    const float* o2    = (const float*)d_in[1];
    const float* gt    = (const float*)d_in[2];
    const float* eps_p = (const float*)d_in[3];
    float* out = (float*)d_out;

    float *gtfps, *f1, *g1v, *f2, *g2v, *emdp;
    float2* cdp;
    int* def_iters;
    cudaGetSymbolAddress((void**)&gtfps, g_gtfps);
    cudaGetSymbolAddress((void**)&f1, g_f1);
    cudaGetSymbolAddress((void**)&g1v, g_g1);
    cudaGetSymbolAddress((void**)&f2, g_f2);
    cudaGetSymbolAddress((void**)&g2v, g_g2);
    cudaGetSymbolAddress((void**)&emdp, g_emdp);
    cudaGetSymbolAddress((void**)&cdp, g_cdp);
    cudaGetSymbolAddress((void**)&def_iters, g_default_iters);

    const int* iters_p = (n_in > 4) ? (const int*)d_in[4] : def_iters;

    size_t fps_smem    = (size_t)N2 * 16 + 128 * 4;
    size_t lse_smem    = (size_t)N2 * 16;
    size_t assign_smem = (size_t)N2 * 16 + (size_t)N2 * 4 + 8 * 4;
    size_t cham_smem   = (size_t)N2 * 16 + 8 * 8;

    cudaFuncSetAttribute(fps_kernel,    cudaFuncAttributeMaxDynamicSharedMemorySize, (int)fps_smem);
    cudaFuncSetAttribute(lse_fused,     cudaFuncAttributeMaxDynamicSharedMemorySize, (int)lse_smem);
    cudaFuncSetAttribute(assign_fused,  cudaFuncAttributeMaxDynamicSharedMemorySize, (int)assign_smem);
    cudaFuncSetAttribute(chamfer_fused, cudaFuncAttributeMaxDynamicSharedMemorySize, (int)cham_smem);

    // Passthrough copies
    cudaMemcpyAsync(out, o1, (size_t)B * N1 * 3 * sizeof(float), cudaMemcpyDeviceToDevice);
    cudaMemcpyAsync(out + B * N1 * 3, o2, (size_t)B * N2 * 3 * sizeof(float), cudaMemcpyDeviceToDevice);

    fps_kernel<<<B, 1024, fps_smem>>>(gt, gtfps);

    // Sinkhorn: first g-step reads f as implicit zero (zmode=1)
    for (int t = 0; t < MAXITER; t++) {
        lse_fused<<<320, 256, lse_smem>>>(gtfps, o1, f1, g1v,  gt, o2, f2, g2v,
                                          eps_p, iters_p, t, (t == 0) ? 1 : 0);
        lse_fused<<<320, 256, lse_smem>>>(o1, gtfps, g1v, f1,  o2, gt, g2v, f2,
                                          eps_p, iters_p, t, 0);
    }
    lse_fused<<<320, 256, lse_smem>>>(gtfps, o1, f1, g1v,  gt, o2, f2, g2v,
                                      eps_p, iters_p, -1, 2);

    assign_fused<<<320, 256, assign_smem>>>(o1, gtfps, g1v, o2, gt, g2v, emdp);
    chamfer_fused<<<832, 256, cham_smem>>>(o1, o2, gt, cdp);
    finalize_kernel<<<1, 32>>>(out);
}

// round 7
// speedup vs baseline: 3.7693x; 1.0629x over previous
#include <cuda_runtime.h>
#include <math.h>

#define B  4
#define N1 1024
#define N2 4096
#define MAXITER 10
#define OUT_SCALARS 61440
#define FULL 0xffffffffu

#define LN2F   0.69314718055994531f
#define LOG2EF 1.44269504088896340f

// ---------------------------------------------------------------------------
// Scratch (device globals; no allocations allowed)
// ---------------------------------------------------------------------------
__device__ float  g_gtfps[B * N1 * 3];
__device__ float  g_f1[B * N1];
__device__ float  g_g1[B * N1];
__device__ float  g_f2[B * N2];
__device__ float  g_g2[B * N2];
__device__ float  g_emdp[320];     // [0,256): emd2 block partials, [256,320): emd1
__device__ float2 g_cdp[832];      // d21 [0,256), d22 [256,512), d11 [512,768), d12 [768,832)
__device__ int    g_default_iters = MAXITER;

// ---------------------------------------------------------------------------
// Packed f32x2 helpers (sm_103a)
// ---------------------------------------------------------------------------
typedef unsigned long long u64;
__device__ __forceinline__ u64 f2pk(float lo, float hi) {
    u64 r; asm("mov.b64 %0, {%1, %2};" : "=l"(r) : "f"(lo), "f"(hi)); return r;
}
__device__ __forceinline__ u64 dup2(float v) {
    u64 r; asm("mov.b64 %0, {%1, %1};" : "=l"(r) : "f"(v)); return r;
}
__device__ __forceinline__ void unpk(u64 v, float& lo, float& hi) {
    asm("mov.b64 {%0, %1}, %2;" : "=f"(lo), "=f"(hi) : "l"(v));
}
__device__ __forceinline__ u64 ffma2(u64 a, u64 b, u64 c) {
    u64 d; asm("fma.rn.f32x2 %0, %1, %2, %3;" : "=l"(d) : "l"(a), "l"(b), "l"(c)); return d;
}
__device__ __forceinline__ u64 fadd2(u64 a, u64 b) {
    u64 d; asm("add.rn.f32x2 %0, %1, %2;" : "=l"(d) : "l"(a), "l"(b)); return d;
}
__device__ __forceinline__ float ex2f(float x) {
    float r; asm("ex2.approx.ftz.f32 %0, %1;" : "=f"(r) : "f"(x)); return r;
}
__device__ __forceinline__ float lg2f(float x) {
    float r; asm("lg2.approx.ftz.f32 %0, %1;" : "=f"(r) : "f"(x)); return r;
}

// ---------------------------------------------------------------------------
// FPS: 1 block of 1024 threads per batch, 1023 sequential argmax steps.
// ---------------------------------------------------------------------------
__global__ __launch_bounds__(1024, 1)
void fps_kernel(const float* __restrict__ gt, float* __restrict__ gtfps) {
    extern __shared__ float smraw_f[];
    float4*   spts = (float4*)smraw_f;            // N2
    unsigned* lum  = (unsigned*)(spts + N2);      // 2*32
    unsigned* lui  = lum + 64;                    // 2*32

    int b = blockIdx.x;
    const float* pts = gt + (size_t)b * N2 * 3;
    int tid = threadIdx.x;

    for (int i = tid; i < N2; i += 1024) {
        float x = pts[3 * i], y = pts[3 * i + 1], z = pts[3 * i + 2];
        spts[i] = make_float4(x, y, z, 0.0f);
    }
    __syncthreads();

    float4 p0 = spts[0];
    float px[4], py[4], pz[4], d[4];
#pragma unroll
    for (int c = 0; c < 4; c++) {
        float4 e = spts[tid + c * 1024];
        px[c] = e.x; py[c] = e.y; pz[c] = e.z;
        float dx = e.x - p0.x, dy = e.y - p0.y, dz = e.z - p0.z;
        d[c] = dx * dx + dy * dy + dz * dz;
    }

    float* outp = gtfps + (size_t)b * N1 * 3;
    if (tid == 0) { outp[0] = p0.x; outp[1] = p0.y; outp[2] = p0.z; }

    int lane = tid & 31, warp = tid >> 5;
    for (int t = 1; t < N1; t++) {
        float bv = d[0]; int bi = tid;
#pragma unroll
        for (int c = 1; c < 4; c++)
            if (d[c] > bv) { bv = d[c]; bi = tid + c * 1024; }

        unsigned ub = __float_as_uint(bv);
        unsigned um = __reduce_max_sync(FULL, ub);
        unsigned cand = (ub == um) ? (unsigned)bi : 0xffffffffu;
        unsigned ui = __reduce_min_sync(FULL, cand);

        int buf = (t & 1) * 32;
        if (lane == 0) { lum[buf + warp] = um; lui[buf + warp] = ui; }
        __syncthreads();

        unsigned vm = lum[buf + lane], vi = lui[buf + lane];
        unsigned gm = __reduce_max_sync(FULL, vm);
        unsigned c2 = (vm == gm) ? vi : 0xffffffffu;
        unsigned gi = __reduce_min_sync(FULL, c2);

        float4 sp = spts[gi];
        if (tid == 0) { outp[3 * t] = sp.x; outp[3 * t + 1] = sp.y; outp[3 * t + 2] = sp.z; }
#pragma unroll
        for (int c = 0; c < 4; c++) {
            float dx = px[c] - sp.x, dy = py[c] - sp.y, dz = pz[c] - sp.z;
            float dd = dx * dx + dy * dy + dz * dz;
            d[c] = fminf(d[c], dd);
        }
    }
}

// ---------------------------------------------------------------------------
// LSE half-step: K-pair-packed SoA tile + per-output duplicated coefficients.
// Tile arrays (float2 over consecutive k): x2, y2, z2, w2 with
// w = (v - ||p||^2) * log2e/eps. Coefficients cq = dup2(2*log2e/eps * q).
// p2-pair = ffma2 chain; pass1 keeps scalar lo/hi maxima (free aliased unpack),
// pass2 accumulates scalar lo/hi exp sums. LSE_nat = ln2*(m2+log2(s)) + cj.
// ---------------------------------------------------------------------------
template<int NSZ>
__device__ __forceinline__ void lse_block(
    const float* __restrict__ Po, const float* __restrict__ Pr,
    const float* __restrict__ vr, float* __restrict__ vo,
    int outbase, float eps, float inv_eps, float loga, float* smraw, int zerov)
{
    float2* x2 = (float2*)smraw;          // NSZ/2
    float2* y2 = x2 + NSZ / 2;
    float2* z2 = y2 + NSZ / 2;
    float2* w2 = z2 + NSZ / 2;

    int tid = threadIdx.x;
    float scal = inv_eps * LOG2EF;
    for (int k2 = tid; k2 < NSZ / 2; k2 += 256) {
        const float* p = Pr + 6 * k2;
        float ax = p[0], ay = p[1], az = p[2];
        float bx = p[3], by = p[4], bz = p[5];
        float va = zerov ? 0.0f : vr[2 * k2];
        float vb = zerov ? 0.0f : vr[2 * k2 + 1];
        x2[k2] = make_float2(ax, bx);
        y2[k2] = make_float2(ay, by);
        z2[k2] = make_float2(az, bz);
        w2[k2] = make_float2((va - (ax * ax + ay * ay + az * az)) * scal,
                             (vb - (bx * bx + by * by + bz * bz)) * scal);
    }
    __syncthreads();

    int lane = tid & 31;
    int j0 = outbase + (tid >> 5) * 8;
    float c1 = 2.0f * scal;
    u64 cqx[8], cqy[8], cqz[8];
#pragma unroll
    for (int o = 0; o < 8; o++) {
        cqx[o] = dup2(c1 * __ldg(Po + 3 * (j0 + o)));
        cqy[o] = dup2(c1 * __ldg(Po + 3 * (j0 + o) + 1));
        cqz[o] = dup2(c1 * __ldg(Po + 3 * (j0 + o) + 2));
    }

    // pass 1: max of p2 over k (lo/hi halves tracked separately)
    float mlo[8], mhi[8];
#pragma unroll
    for (int o = 0; o < 8; o++) { mlo[o] = -3.4e38f; mhi[o] = -3.4e38f; }
#pragma unroll 2
    for (int it = 0; it < NSZ / 64; ++it) {
        int k2 = it * 32 + lane;
        float2 ex = x2[k2], ey = y2[k2], ez = z2[k2], ew = w2[k2];
        u64 xx = f2pk(ex.x, ex.y), yy = f2pk(ey.x, ey.y);
        u64 zz = f2pk(ez.x, ez.y), ww = f2pk(ew.x, ew.y);
#pragma unroll
        for (int o = 0; o < 8; o++) {
            u64 t = ffma2(xx, cqx[o], ffma2(yy, cqy[o], ffma2(zz, cqz[o], ww)));
            float lo, hi; unpk(t, lo, hi);
            mlo[o] = fmaxf(mlo[o], lo);
            mhi[o] = fmaxf(mhi[o], hi);
        }
    }
    float m[8];
#pragma unroll
    for (int o = 0; o < 8; o++) {
        m[o] = fmaxf(mlo[o], mhi[o]);
#pragma unroll
        for (int off = 16; off; off >>= 1)
            m[o] = fmaxf(m[o], __shfl_xor_sync(FULL, m[o], off));
    }
    u64 nm2[8];
#pragma unroll
    for (int o = 0; o < 8; o++) nm2[o] = dup2(-m[o]);

    // pass 2: branchless sum of 2^(p2 - m2)
    float slo[8], shi[8];
#pragma unroll
    for (int o = 0; o < 8; o++) { slo[o] = 0.0f; shi[o] = 0.0f; }
#pragma unroll 2
    for (int it = 0; it < NSZ / 64; ++it) {
        int k2 = it * 32 + lane;
        float2 ex = x2[k2], ey = y2[k2], ez = z2[k2], ew = w2[k2];
        u64 xx = f2pk(ex.x, ex.y), yy = f2pk(ey.x, ey.y);
        u64 zz = f2pk(ez.x, ez.y), ww = f2pk(ew.x, ew.y);
#pragma unroll
        for (int o = 0; o < 8; o++) {
            u64 t = ffma2(xx, cqx[o], ffma2(yy, cqy[o], ffma2(zz, cqz[o], ww)));
            t = fadd2(t, nm2[o]);
            float lo, hi; unpk(t, lo, hi);
            slo[o] += ex2f(lo);
            shi[o] += ex2f(hi);
        }
    }
    float s[8];
#pragma unroll
    for (int o = 0; o < 8; o++) {
        s[o] = slo[o] + shi[o];
#pragma unroll
        for (int off = 16; off; off >>= 1)
            s[o] += __shfl_xor_sync(FULL, s[o], off);
    }

#pragma unroll
    for (int o = 0; o < 8; o++)
        if (lane == o) {
            float qx = __ldg(Po + 3 * (j0 + o));
            float qy = __ldg(Po + 3 * (j0 + o) + 1);
            float qz = __ldg(Po + 3 * (j0 + o) + 2);
            float cj = fmaf(-(qx * qx + qy * qy + qz * qz), inv_eps, loga);
            vo[j0 + o] = -eps * (LN2F * (m[o] + lg2f(s[o])) + cj);
        }
}

// zmode: 0 = read vr; 1 = treat vr as zero; 2 = zero iff *iters <= 0
__global__ __launch_bounds__(256, 2)
void lse_fused(const float* Po1, const float* Pr1, const float* vr1, float* vo1,
               const float* Po2, const float* Pr2, const float* vr2, float* vo2,
               const float* __restrict__ eps_p, const int* __restrict__ iters_p,
               int t, int zmode)
{
    int iters = __ldg(iters_p);
    if (t >= 0 && t >= iters) return;
    int zerov = (zmode == 1) || (zmode == 2 && iters <= 0);
    extern __shared__ float smraw_l[];
    float eps = __ldg(eps_p), inv = 1.0f / eps;
    int bx = blockIdx.x;
    if (bx < 256) {
        int b = bx >> 6;
        lse_block<N2>(Po2 + (size_t)b * N2 * 3, Pr2 + (size_t)b * N2 * 3,
                      vr2 + (size_t)b * N2, vo2 + (size_t)b * N2,
                      (bx & 63) * 64, eps, inv, -8.3177661667193436f, smraw_l, zerov);
    } else {
        int g = bx - 256, b = g >> 4;
        lse_block<N1>(Po1 + (size_t)b * N1 * 3, Pr1 + (size_t)b * N1 * 3,
                      vr1 + (size_t)b * N1, vo1 + (size_t)b * N1,
                      (g & 15) * 64, eps, inv, -6.9314718055994531f, smraw_l, zerov);
    }
}

// ---------------------------------------------------------------------------
// Fused assignment (exact first-index argmax of g_j - C_ij, then sum sqrt(C))
// ---------------------------------------------------------------------------
__device__ __forceinline__ unsigned sortkey(float f) {
    unsigned u = __float_as_uint(f);
    return ((int)u < 0) ? ~u : (u | 0x80000000u);
}

template<int NSZ>
__device__ __forceinline__ void assign_block(
    const float* __restrict__ Px, const float* __restrict__ Py,
    const float* __restrict__ gv, float* __restrict__ partial,
    int outbase, int pidx, char* smraw)
{
    float4* tile = (float4*)smraw;          // NSZ: {x,y,z, g-ny}
    float*  garr = (float*)(tile + NSZ);    // NSZ: g
    float*  wred = garr + NSZ;              // 8
    int tid = threadIdx.x;
    for (int k = tid; k < NSZ; k += 256) {
        float x = Py[3 * k], y = Py[3 * k + 1], z = Py[3 * k + 2];
        float ny = x * x + y * y + z * z;
        float gk = gv[k];
        garr[k] = gk;
        tile[k] = make_float4(x, y, z, gk - ny);
    }
    __syncthreads();

    int lane = tid & 31, w = tid >> 5;
    int j0 = outbase + w * 8;
    float c2x[8], c2y[8], c2z[8], na[8], bv[8]; int bi[8];
#pragma unroll
    for (int o = 0; o < 8; o++) {
        float qx = __ldg(Px + 3 * (j0 + o));
        float qy = __ldg(Px + 3 * (j0 + o) + 1);
        float qz = __ldg(Px + 3 * (j0 + o) + 2);
        c2x[o] = 2.0f * qx; c2y[o] = 2.0f * qy; c2z[o] = 2.0f * qz;
        na[o] = qx * qx + qy * qy + qz * qz;
        bv[o] = -3.4e38f; bi[o] = 0;
    }
#pragma unroll 2
    for (int it = 0; it < NSZ / 32; ++it) {
        int k = it * 32 + lane;
        float4 e = tile[k];
#pragma unroll
        for (int o = 0; o < 8; o++) {
            float v = fmaf(e.x, c2x[o], fmaf(e.y, c2y[o], fmaf(e.z, c2z[o], e.w)));
            if (v > bv[o]) { bv[o] = v; bi[o] = k; }
        }
    }
    float acc = 0.0f;
#pragma unroll
    for (int o = 0; o < 8; o++) {
        unsigned key  = sortkey(bv[o]);
        unsigned kmax = __reduce_max_sync(FULL, key);
        unsigned cand = (key == kmax) ? (unsigned)bi[o] : 0xffffffffu;
        unsigned imin = __reduce_min_sync(FULL, cand);
        if (key == kmax && (unsigned)bi[o] == imin) {
            float C = fmaxf(na[o] + garr[bi[o]] - bv[o], 0.0f);
            acc += sqrtf(C);
        }
    }
#pragma unroll
    for (int off = 16; off; off >>= 1) acc += __shfl_xor_sync(FULL, acc, off);
    if (lane == 0) wred[w] = acc;
    __syncthreads();
    if (tid == 0) {
        float sum = 0.0f;
        for (int i = 0; i < 8; i++) sum += wred[i];
        partial[pidx] = sum;
    }
}

__global__ __launch_bounds__(256)
void assign_fused(const float* Px1, const float* Py1, const float* g1v,
                  const float* Px2, const float* Py2, const float* g2v,
                  float* partial)
{
    extern __shared__ char smraw_a[];
    int bx = blockIdx.x;
    if (bx < 256) {
        int b = bx >> 6;
        assign_block<N2>(Px2 + (size_t)b * N2 * 3, Py2 + (size_t)b * N2 * 3,
                         g2v + (size_t)b * N2, partial, (bx & 63) * 64, bx, smraw_a);
    } else {
        int g = bx - 256, b = g >> 4;
        assign_block<N1>(Px1 + (size_t)b * N1 * 3, Py1 + (size_t)b * N1 * 3,
                         g1v + (size_t)b * N1, partial, (g & 15) * 64, bx, smraw_a);
    }
}

// ---------------------------------------------------------------------------
// Fused chamfer (packed f32x2 over output pairs)
// ---------------------------------------------------------------------------
template<int NSZ>
__device__ __forceinline__ void chamfer_block(
    const float* __restrict__ Pa, const float* __restrict__ Pb,
    float2* __restrict__ partial, int outbase, int pidx, char* smraw)
{
    float4* tile = (float4*)smraw;            // NSZ {x,y,z,ny}
    float2* wred = (float2*)(tile + NSZ);     // 8
    int tid = threadIdx.x;
    for (int k = tid; k < NSZ; k += 256) {
        float x = Pb[3 * k], y = Pb[3 * k + 1], z = Pb[3 * k + 2];
        tile[k] = make_float4(x, y, z, x * x + y * y + z * z);
    }
    __syncthreads();

    int lane = tid & 31, w = tid >> 5;
    int j0 = outbase + w * 8;
    u64 mx2[4], my2[4], mz2[4];
    float na[8], mn[8];
#pragma unroll
    for (int p = 0; p < 4; p++) {
        int ja = j0 + 2 * p, jb = ja + 1;
        float ax = __ldg(Pa + 3 * ja),     bxq = __ldg(Pa + 3 * jb);
        float ay = __ldg(Pa + 3 * ja + 1), by = __ldg(Pa + 3 * jb + 1);
        float az = __ldg(Pa + 3 * ja + 2), bz = __ldg(Pa + 3 * jb + 2);
        mx2[p] = f2pk(-2.0f * ax, -2.0f * bxq);
        my2[p] = f2pk(-2.0f * ay, -2.0f * by);
        mz2[p] = f2pk(-2.0f * az, -2.0f * bz);
        na[2 * p]     = ax * ax + ay * ay + az * az;
        na[2 * p + 1] = bxq * bxq + by * by + bz * bz;
        mn[2 * p] = 3.4e38f; mn[2 * p + 1] = 3.4e38f;
    }
#pragma unroll 2
    for (int it = 0; it < NSZ / 32; ++it) {
        float4 e = tile[it * 32 + lane];
        u64 xx = dup2(e.x), yy = dup2(e.y), zz = dup2(e.z), ww = dup2(e.w);
#pragma unroll
        for (int p = 0; p < 4; p++) {
            u64 t = ffma2(xx, mx2[p], ffma2(yy, my2[p], ffma2(zz, mz2[p], ww)));
            float lo, hi; unpk(t, lo, hi);
            mn[2 * p]     = fminf(mn[2 * p], lo);
            mn[2 * p + 1] = fminf(mn[2 * p + 1], hi);
        }
    }
#pragma unroll
    for (int o = 0; o < 8; o++)
#pragma unroll
        for (int off = 16; off; off >>= 1)
            mn[o] = fminf(mn[o], __shfl_xor_sync(FULL, mn[o], off));

    if (lane == 0) {
        float ssq = 0.0f, sd = 0.0f;
#pragma unroll
        for (int o = 0; o < 8; o++) {
            float d = fmaxf(mn[o] + na[o], 0.0f);
            ssq += sqrtf(d); sd += d;
        }
        wred[w] = make_float2(ssq, sd);
    }
    __syncthreads();
    if (tid == 0) {
        float a = 0.0f, bm = 0.0f;
        for (int i = 0; i < 8; i++) { a += wred[i].x; bm += wred[i].y; }
        partial[pidx] = make_float2(a, bm);
    }
}

__global__ __launch_bounds__(256)
void chamfer_fused(const float* o1, const float* o2, const float* gt,
                   float2* partial)
{
    extern __shared__ char smraw_c[];
    int bx = blockIdx.x;
    if (bx < 256) {               // d21: a=gt (4096 outs), reduce o2 (4096)
        int b = bx >> 6;
        chamfer_block<N2>(gt + (size_t)b * N2 * 3, o2 + (size_t)b * N2 * 3,
                          partial, (bx & 63) * 64, bx, smraw_c);
    } else if (bx < 512) {        // d22: a=o2, reduce gt
        int g = bx - 256, b = g >> 6;
        chamfer_block<N2>(o2 + (size_t)b * N2 * 3, gt + (size_t)b * N2 * 3,
                          partial, (g & 63) * 64, bx, smraw_c);
    } else if (bx < 768) {        // d11: a=gt (4096 outs), reduce o1 (1024)
        int g = bx - 512, b = g >> 6;
        chamfer_block<N1>(gt + (size_t)b * N2 * 3, o1 + (size_t)b * N1 * 3,
                          partial, (g & 63) * 64, bx, smraw_c);
    } else {                      // d12: a=o1 (1024 outs), reduce gt (4096)
        int g = bx - 768, b = g >> 4;
        chamfer_block<N2>(o1 + (size_t)b * N1 * 3, gt + (size_t)b * N2 * 3,
                          partial, (g & 15) * 64, bx, smraw_c);
    }
}

// ---------------------------------------------------------------------------
__global__ void finalize_kernel(float* __restrict__ out) {
    int b = threadIdx.x;
    if (b >= B) return;

    float s = 0.0f;
    for (int i = 0; i < 16; i++) s += g_emdp[256 + b * 16 + i];
    out[OUT_SCALARS + 0 + b] = s / (float)N1;                       // emd1

    s = 0.0f;
    for (int i = 0; i < 64; i++) s += g_emdp[b * 64 + i];
    out[OUT_SCALARS + 4 + b] = s / (float)N2;                       // emd2

    float ss21 = 0, sd21 = 0, ss22 = 0, sd22 = 0;
    float ss11 = 0, sd11 = 0, ss12 = 0, sd12 = 0;
    for (int i = 0; i < 64; i++) { float2 v = g_cdp[      b * 64 + i]; ss21 += v.x; sd21 += v.y; }
    for (int i = 0; i < 64; i++) { float2 v = g_cdp[256 + b * 64 + i]; ss22 += v.x; sd22 += v.y; }
    for (int i = 0; i < 64; i++) { float2 v = g_cdp[512 + b * 64 + i]; ss11 += v.x; sd11 += v.y; }
    for (int i = 0; i < 16; i++) { float2 v = g_cdp[768 + b * 16 + i]; ss12 += v.x; sd12 += v.y; }

    out[OUT_SCALARS + 8  + b] = (ss11 / (float)N2 + ss12 / (float)N1) * 0.5f;  // cd_p1
    out[OUT_SCALARS + 12 + b] = (ss21 / (float)N2 + ss22 / (float)N2) * 0.5f;  // cd_p2
    out[OUT_SCALARS + 16 + b] =  sd11 / (float)N2 + sd12 / (float)N1;          // cd_t1
    out[OUT_SCALARS + 20 + b] =  sd21 / (float)N2 + sd22 / (float)N2;          // cd_t2
}

// ---------------------------------------------------------------------------
extern "C" void kernel_launch(void* const* d_in, const int* in_sizes, int n_in,
                              void* d_out, int out_size) {
    const float* o1    = (const float*)d_in[0];
    const float* o2    = (const float*)d_in[1];
    const float* gt    = (const float*)d_in[2];
    const float* eps_p = (const float*)d_in[3];
    float* out = (float*)d_out;

    float *gtfps, *f1, *g1v, *f2, *g2v, *emdp;
    float2* cdp;
    int* def_iters;
    cudaGetSymbolAddress((void**)&gtfps, g_gtfps);
    cudaGetSymbolAddress((void**)&f1, g_f1);
    cudaGetSymbolAddress((void**)&g1v, g_g1);
    cudaGetSymbolAddress((void**)&f2, g_f2);
    cudaGetSymbolAddress((void**)&g2v, g_g2);
    cudaGetSymbolAddress((void**)&emdp, g_emdp);
    cudaGetSymbolAddress((void**)&cdp, g_cdp);
    cudaGetSymbolAddress((void**)&def_iters, g_default_iters);

    const int* iters_p = (n_in > 4) ? (const int*)d_in[4] : def_iters;

    size_t fps_smem    = (size_t)N2 * 16 + 128 * 4;
    size_t lse_smem    = (size_t)N2 * 16;                 // 4 SoA float2 arrays
    size_t assign_smem = (size_t)N2 * 16 + (size_t)N2 * 4 + 8 * 4;
    size_t cham_smem   = (size_t)N2 * 16 + 8 * 8;

    cudaFuncSetAttribute(fps_kernel,    cudaFuncAttributeMaxDynamicSharedMemorySize, (int)fps_smem);
    cudaFuncSetAttribute(lse_fused,     cudaFuncAttributeMaxDynamicSharedMemorySize, (int)lse_smem);
    cudaFuncSetAttribute(assign_fused,  cudaFuncAttributeMaxDynamicSharedMemorySize, (int)assign_smem);
    cudaFuncSetAttribute(chamfer_fused, cudaFuncAttributeMaxDynamicSharedMemorySize, (int)cham_smem);

    // Passthrough copies
    cudaMemcpyAsync(out, o1, (size_t)B * N1 * 3 * sizeof(float), cudaMemcpyDeviceToDevice);
    cudaMemcpyAsync(out + B * N1 * 3, o2, (size_t)B * N2 * 3 * sizeof(float), cudaMemcpyDeviceToDevice);

    fps_kernel<<<B, 1024, fps_smem>>>(gt, gtfps);

    // Sinkhorn: first g-step reads f as implicit zero (zmode=1)
    for (int t = 0; t < MAXITER; t++) {
        lse_fused<<<320, 256, lse_smem>>>(gtfps, o1, f1, g1v,  gt, o2, f2, g2v,
                                          eps_p, iters_p, t, (t == 0) ? 1 : 0);
        lse_fused<<<320, 256, lse_smem>>>(o1, gtfps, g1v, f1,  o2, gt, g2v, f2,
                                          eps_p, iters_p, t, 0);
    }
    lse_fused<<<320, 256, lse_smem>>>(gtfps, o1, f1, g1v,  gt, o2, f2, g2v,
                                      eps_p, iters_p, -1, 2);

    assign_fused<<<320, 256, assign_smem>>>(o1, gtfps, g1v, o2, gt, g2v, emdp);
    chamfer_fused<<<832, 256, cham_smem>>>(o1, o2, gt, cdp);
    finalize_kernel<<<1, 32>>>(out);
}